// round 4
// baseline (speedup 1.0000x reference)
#include <cuda_runtime.h>
#include <math.h>
#include <stdint.h>

// Problem dims
constexpr int BATCH = 2;
constexpr int SEQ   = 1024;
constexpr int DM    = 1024;
constexpr int DIN   = 2048;
constexpr int NST   = 16;
constexpr int FH    = 2752;
constexpr int ROWS  = BATCH * SEQ;  // 2048

// Scratch
__device__ float g_h [ROWS * DM];
__device__ float g_a [ROWS * DIN];
__device__ float g_b [ROWS * DIN];
__device__ float g_y [ROWS * DIN];
__device__ float g_x2[ROWS * DM];
__device__ float g_bc[ROWS * 2 * NST];
__device__ float g_g [ROWS * FH];

constexpr int S = 20;   // smem stride (floats): conflict-free for frag pattern

__device__ __forceinline__ uint32_t f2tf32(float f) {
    uint32_t u;
    asm("cvt.rna.tf32.f32 %0, %1;" : "=r"(u) : "f"(f));
    return u;
}
__device__ __forceinline__ void mma_tf32(float c[4],
                                         uint32_t a0, uint32_t a1, uint32_t a2, uint32_t a3,
                                         uint32_t b0, uint32_t b1) {
    asm volatile(
        "mma.sync.aligned.m16n8k8.row.col.f32.tf32.tf32.f32 "
        "{%0,%1,%2,%3}, {%4,%5,%6,%7}, {%8,%9}, {%0,%1,%2,%3};"
        : "+f"(c[0]), "+f"(c[1]), "+f"(c[2]), "+f"(c[3])
        : "r"(a0), "r"(a1), "r"(a2), "r"(a3), "r"(b0), "r"(b1));
}

enum { EP_ADD = 0, EP_SOFTPLUS };
enum { DEP_GATE = 0, DEP_SILU };

__device__ __forceinline__ float sigm(float x) { return 1.0f / (1.0f + expf(-x)); }
__device__ __forceinline__ float sftp(float x) { return (x > 20.0f) ? x : log1pf(expf(x)); }

__device__ __forceinline__ void cvt_store(float* p, float4 v) {
    uint32_t* u = (uint32_t*)p;
    u[0] = f2tf32(v.x); u[1] = f2tf32(v.y); u[2] = f2tf32(v.z); u[3] = f2tf32(v.w);
}

// ---------------------------------------------------------------------------
// Single-B tf32 GEMM: C = epilogue(A[M,K] @ W[N,K]^T).  BN=128, 8 warps,
// 256 threads.  BM/WM/WN template params.  BK=16, double-buffered.
// ---------------------------------------------------------------------------
template<int EP, int BM, int WM, int WN>
__global__ void __launch_bounds__(256) sgl_gemm(
    const float* __restrict__ A, const float* __restrict__ W,
    const float* __restrict__ R, const float* __restrict__ bias,
    float* __restrict__ C, int M, int N, int K)
{
    constexpr int WN_CNT = 128 / WN;
    constexpr int MT = WM / 16, NT = WN / 8;
    constexpr int AJ = BM / 64;          // float4 loads/thread for A
    extern __shared__ float smem[];
    float* As = smem;                    // [2][BM*S]
    float* Bs = smem + 2 * BM * S;       // [2][128*S]

    const int tid  = threadIdx.x;
    const int wid  = tid >> 5, lane = tid & 31;
    const int wm   = wid / WN_CNT, wn = wid % WN_CNT;
    const int bm   = blockIdx.y * BM, bn = blockIdx.x << 7;
    const int lr   = lane >> 2, lc = lane & 3;

    float acc[MT][NT][4];
    #pragma unroll
    for (int i = 0; i < MT; i++)
        #pragma unroll
        for (int j = 0; j < NT; j++)
            #pragma unroll
            for (int q = 0; q < 4; q++) acc[i][j][q] = 0.0f;

    const int row0 = tid >> 2;           // +64 per j
    const int kcol = (tid & 3) << 2;
    const int NS   = K >> 4;

    float4 areg[AJ], breg[2];

    #pragma unroll
    for (int j = 0; j < AJ; j++)
        areg[j] = *(const float4*)(A + (size_t)(bm + row0 + 64 * j) * K + kcol);
    #pragma unroll
    for (int j = 0; j < 2; j++) {
        const int row = row0 + 64 * j;
        breg[j] = (bn + row < N) ? *(const float4*)(W + (size_t)(bn + row) * K + kcol)
                                 : make_float4(0.f, 0.f, 0.f, 0.f);
    }
    #pragma unroll
    for (int j = 0; j < AJ; j++)
        cvt_store(&As[(row0 + 64 * j) * S + kcol], areg[j]);
    #pragma unroll
    for (int j = 0; j < 2; j++)
        cvt_store(&Bs[(row0 + 64 * j) * S + kcol], breg[j]);
    __syncthreads();

    for (int ks = 0; ks < NS; ks++) {
        const int buf = ks & 1;
        if (ks + 1 < NS) {
            const int k0 = (ks + 1) << 4;
            #pragma unroll
            for (int j = 0; j < AJ; j++)
                areg[j] = *(const float4*)(A + (size_t)(bm + row0 + 64 * j) * K + k0 + kcol);
            #pragma unroll
            for (int j = 0; j < 2; j++) {
                const int row = row0 + 64 * j;
                breg[j] = (bn + row < N) ? *(const float4*)(W + (size_t)(bn + row) * K + k0 + kcol)
                                         : make_float4(0.f, 0.f, 0.f, 0.f);
            }
        }

        const uint32_t* Asb = (const uint32_t*)&As[buf * BM * S];
        const uint32_t* Bsb = (const uint32_t*)&Bs[buf * 128 * S];
        #pragma unroll
        for (int kc = 0; kc < 2; kc++) {
            uint32_t af[MT][4], bf[NT][2];
            #pragma unroll
            for (int tm = 0; tm < MT; tm++) {
                const int base = (wm * WM + tm * 16 + lr) * S + kc * 8 + lc;
                af[tm][0] = Asb[base];
                af[tm][1] = Asb[base + 8 * S];
                af[tm][2] = Asb[base + 4];
                af[tm][3] = Asb[base + 8 * S + 4];
            }
            #pragma unroll
            for (int tn = 0; tn < NT; tn++) {
                const int base = (wn * WN + tn * 8 + lr) * S + kc * 8 + lc;
                bf[tn][0] = Bsb[base];
                bf[tn][1] = Bsb[base + 4];
            }
            #pragma unroll
            for (int tm = 0; tm < MT; tm++)
                #pragma unroll
                for (int tn = 0; tn < NT; tn++)
                    mma_tf32(acc[tm][tn], af[tm][0], af[tm][1], af[tm][2], af[tm][3],
                             bf[tn][0], bf[tn][1]);
        }

        if (ks + 1 < NS) {
            const int nb = (ks + 1) & 1;
            #pragma unroll
            for (int j = 0; j < AJ; j++)
                cvt_store(&As[nb * BM * S + (row0 + 64 * j) * S + kcol], areg[j]);
            #pragma unroll
            for (int j = 0; j < 2; j++)
                cvt_store(&Bs[nb * 128 * S + (row0 + 64 * j) * S + kcol], breg[j]);
            __syncthreads();
        }
    }

    #pragma unroll
    for (int tm = 0; tm < MT; tm++) {
        const int row = bm + wm * WM + tm * 16 + lr;
        #pragma unroll
        for (int tn = 0; tn < NT; tn++) {
            const int col = bn + wn * WN + tn * 8 + lc * 2;
            if (col < N) {
                const size_t o0 = (size_t)row * N + col;
                const size_t o1 = (size_t)(row + 8) * N + col;
                float2 v0 = make_float2(acc[tm][tn][0], acc[tm][tn][1]);
                float2 v1 = make_float2(acc[tm][tn][2], acc[tm][tn][3]);
                if (EP == EP_ADD) {
                    const float2 r0 = *(const float2*)(R + o0);
                    const float2 r1 = *(const float2*)(R + o1);
                    v0.x += r0.x; v0.y += r0.y; v1.x += r1.x; v1.y += r1.y;
                } else { // EP_SOFTPLUS
                    const float2 bv = *(const float2*)(bias + col);
                    v0.x = sftp(v0.x + bv.x); v0.y = sftp(v0.y + bv.y);
                    v1.x = sftp(v1.x + bv.x); v1.y = sftp(v1.y + bv.y);
                }
                *(float2*)(C + o0) = v0;
                *(float2*)(C + o1) = v1;
            }
        }
    }
}

// ---------------------------------------------------------------------------
// Dual-B tf32 GEMM: one A tile, two weight matrices.
//   DEP_GATE: C = (A@W1^T) * sigmoid(A@W2^T)
//   DEP_SILU: C = silu(A@W1^T) * (A@W2^T)
// BM=128, BN=128, 8 warps (2x4), warp tile 64x32.
// ---------------------------------------------------------------------------
template<int DEP>
__global__ void __launch_bounds__(256) dual_gemm(
    const float* __restrict__ A, const float* __restrict__ W1,
    const float* __restrict__ W2, float* __restrict__ C,
    int M, int N, int K)
{
    constexpr int BM = 128, WM = 64, WN = 32, MT = 4, NT = 4;
    extern __shared__ float smem[];
    float* As  = smem;                    // [2][128*S]
    float* B1s = smem + 2 * 128 * S;
    float* B2s = smem + 4 * 128 * S;

    const int tid  = threadIdx.x;
    const int wid  = tid >> 5, lane = tid & 31;
    const int wm   = wid >> 2, wn = wid & 3;
    const int bm   = blockIdx.y << 7, bn = blockIdx.x << 7;
    const int lr   = lane >> 2, lc = lane & 3;

    float acc1[MT][NT][4], acc2[MT][NT][4];
    #pragma unroll
    for (int i = 0; i < MT; i++)
        #pragma unroll
        for (int j = 0; j < NT; j++)
            #pragma unroll
            for (int q = 0; q < 4; q++) { acc1[i][j][q] = 0.0f; acc2[i][j][q] = 0.0f; }

    const int row0 = tid >> 2;
    const int kcol = (tid & 3) << 2;
    const int NS   = K >> 4;

    float4 ar[2], b1r[2], b2r[2];

    #pragma unroll
    for (int j = 0; j < 2; j++) {
        const int row = row0 + 64 * j;
        ar[j]  = *(const float4*)(A + (size_t)(bm + row) * K + kcol);
        const bool v = (bn + row) < N;
        b1r[j] = v ? *(const float4*)(W1 + (size_t)(bn + row) * K + kcol) : make_float4(0,0,0,0);
        b2r[j] = v ? *(const float4*)(W2 + (size_t)(bn + row) * K + kcol) : make_float4(0,0,0,0);
    }
    #pragma unroll
    for (int j = 0; j < 2; j++) {
        const int off = (row0 + 64 * j) * S + kcol;
        cvt_store(&As [off], ar[j]);
        cvt_store(&B1s[off], b1r[j]);
        cvt_store(&B2s[off], b2r[j]);
    }
    __syncthreads();

    for (int ks = 0; ks < NS; ks++) {
        const int buf = ks & 1;
        if (ks + 1 < NS) {
            const int k0 = (ks + 1) << 4;
            #pragma unroll
            for (int j = 0; j < 2; j++) {
                const int row = row0 + 64 * j;
                ar[j]  = *(const float4*)(A + (size_t)(bm + row) * K + k0 + kcol);
                const bool v = (bn + row) < N;
                b1r[j] = v ? *(const float4*)(W1 + (size_t)(bn + row) * K + k0 + kcol) : make_float4(0,0,0,0);
                b2r[j] = v ? *(const float4*)(W2 + (size_t)(bn + row) * K + k0 + kcol) : make_float4(0,0,0,0);
            }
        }

        const uint32_t* Asb  = (const uint32_t*)&As [buf * 128 * S];
        const uint32_t* B1sb = (const uint32_t*)&B1s[buf * 128 * S];
        const uint32_t* B2sb = (const uint32_t*)&B2s[buf * 128 * S];
        #pragma unroll
        for (int kc = 0; kc < 2; kc++) {
            uint32_t af[MT][4], bf1[NT][2], bf2[NT][2];
            #pragma unroll
            for (int tm = 0; tm < MT; tm++) {
                const int base = (wm * WM + tm * 16 + lr) * S + kc * 8 + lc;
                af[tm][0] = Asb[base];
                af[tm][1] = Asb[base + 8 * S];
                af[tm][2] = Asb[base + 4];
                af[tm][3] = Asb[base + 8 * S + 4];
            }
            #pragma unroll
            for (int tn = 0; tn < NT; tn++) {
                const int base = (wn * WN + tn * 8 + lr) * S + kc * 8 + lc;
                bf1[tn][0] = B1sb[base]; bf1[tn][1] = B1sb[base + 4];
                bf2[tn][0] = B2sb[base]; bf2[tn][1] = B2sb[base + 4];
            }
            #pragma unroll
            for (int tm = 0; tm < MT; tm++)
                #pragma unroll
                for (int tn = 0; tn < NT; tn++) {
                    mma_tf32(acc1[tm][tn], af[tm][0], af[tm][1], af[tm][2], af[tm][3],
                             bf1[tn][0], bf1[tn][1]);
                    mma_tf32(acc2[tm][tn], af[tm][0], af[tm][1], af[tm][2], af[tm][3],
                             bf2[tn][0], bf2[tn][1]);
                }
        }

        if (ks + 1 < NS) {
            const int nb = (ks + 1) & 1;
            #pragma unroll
            for (int j = 0; j < 2; j++) {
                const int off = nb * 128 * S + (row0 + 64 * j) * S + kcol;
                cvt_store(&As [off], ar[j]);
                cvt_store(&B1s[off], b1r[j]);
                cvt_store(&B2s[off], b2r[j]);
            }
            __syncthreads();
        }
    }

    #pragma unroll
    for (int tm = 0; tm < MT; tm++) {
        const int row = bm + wm * WM + tm * 16 + lr;
        #pragma unroll
        for (int tn = 0; tn < NT; tn++) {
            const int col = bn + wn * WN + tn * 8 + lc * 2;
            if (col < N) {
                #pragma unroll
                for (int half = 0; half < 2; half++) {
                    const size_t o = (size_t)(row + half * 8) * N + col;
                    float a0 = acc1[tm][tn][half * 2], a1 = acc1[tm][tn][half * 2 + 1];
                    float g0 = acc2[tm][tn][half * 2], g1 = acc2[tm][tn][half * 2 + 1];
                    float2 v;
                    if (DEP == DEP_GATE) {        // z = in * sigmoid(gate)
                        v.x = a0 * sigm(g0); v.y = a1 * sigm(g1);
                    } else {                      // silu(gate) * up
                        v.x = a0 * sigm(a0) * g0; v.y = a1 * sigm(a1) * g1;
                    }
                    *(float2*)(C + o) = v;
                }
            }
        }
    }
}

// ---------------------------------------------------------------------------
// RMSNorm
// ---------------------------------------------------------------------------
__global__ void __launch_bounds__(256) rmsnorm_kernel(
    const float* __restrict__ x, const float* __restrict__ w, float* __restrict__ out)
{
    __shared__ float red[8];
    const int row = blockIdx.x;
    const int tid = threadIdx.x;
    const float4 v = ((const float4*)(x + (size_t)row * DM))[tid];
    float s = v.x*v.x + v.y*v.y + v.z*v.z + v.w*v.w;
    #pragma unroll
    for (int o = 16; o; o >>= 1) s += __shfl_xor_sync(0xffffffffu, s, o);
    if ((tid & 31) == 0) red[tid >> 5] = s;
    __syncthreads();
    if (tid < 8) {
        float t = red[tid];
        #pragma unroll
        for (int o = 4; o; o >>= 1) t += __shfl_xor_sync(0xffu, t, o);
        if (tid == 0) red[0] = t;
    }
    __syncthreads();
    const float scale = rsqrtf(red[0] * (1.0f / DM) + 1e-6f);
    const float4 wv = ((const float4*)w)[tid];
    float4 o4;
    o4.x = v.x * scale * wv.x; o4.y = v.y * scale * wv.y;
    o4.z = v.z * scale * wv.z; o4.w = v.w * scale * wv.w;
    ((float4*)(out + (size_t)row * DM))[tid] = o4;
}

// ---------------------------------------------------------------------------
// BC = z @ x_proj^T (N=32, K=DIN)
// ---------------------------------------------------------------------------
__global__ void __launch_bounds__(256) bc_kernel(const float* __restrict__ Wx)
{
    const int row  = blockIdx.x;
    const int tid  = threadIdx.x;
    const int w    = tid >> 5;
    const int lane = tid & 31;
    const float* zr = g_a + (size_t)row * DIN;
    float acc[4] = {0.f, 0.f, 0.f, 0.f};
    for (int k = lane; k < DIN; k += 32) {
        const float zv = zr[k];
        #pragma unroll
        for (int j = 0; j < 4; j++)
            acc[j] = fmaf(zv, Wx[(size_t)(w * 4 + j) * DIN + k], acc[j]);
    }
    #pragma unroll
    for (int j = 0; j < 4; j++) {
        float s = acc[j];
        #pragma unroll
        for (int o = 16; o; o >>= 1) s += __shfl_xor_sync(0xffffffffu, s, o);
        if (lane == 0) g_bc[(size_t)row * 32 + w * 4 + j] = s;
    }
}

// ---------------------------------------------------------------------------
// Selective scan (16 lanes per channel)
// ---------------------------------------------------------------------------
__global__ void __launch_bounds__(256) scan_kernel(
    const float* __restrict__ A_log, const float* __restrict__ Dp)
{
    const int tid = threadIdx.x;
    const int ch  = blockIdx.x * 16 + (tid >> 4);
    const int n   = tid & 15;
    const int b   = ch / DIN;
    const int e   = ch % DIN;

    const float An  = -__expf(A_log[(size_t)e * NST + n]);
    const float dpe = Dp[e];

    const float* dtp = g_b  + (size_t)b * SEQ * DIN + e;
    const float* zp  = g_a  + (size_t)b * SEQ * DIN + e;
    const float* bcp = g_bc + (size_t)b * SEQ * 32;
    float*       yp  = g_y  + (size_t)b * SEQ * DIN + e;

    float state = 0.0f;
    for (int t = 0; t < SEQ; t++) {
        const float dtv = dtp[(size_t)t * DIN];
        const float zv  = zp [(size_t)t * DIN];
        const float Bn  = bcp[t * 32 + n];
        const float Cn  = bcp[t * 32 + 16 + n];
        state = __expf(dtv * An) * state + dtv * zv * Bn;
        float s = state * Cn;
        s += __shfl_xor_sync(0xffffffffu, s, 8);
        s += __shfl_xor_sync(0xffffffffu, s, 4);
        s += __shfl_xor_sync(0xffffffffu, s, 2);
        s += __shfl_xor_sync(0xffffffffu, s, 1);
        if (n == 0) yp[(size_t)t * DIN] = s + zv * dpe;
    }
}

// ---------------------------------------------------------------------------
// Launch
// ---------------------------------------------------------------------------
extern "C" void kernel_launch(void* const* d_in, const int* in_sizes, int n_in,
                              void* d_out, int out_size)
{
    const float* x          = (const float*)d_in[0];
    const float* norm1_w    = (const float*)d_in[1];
    const float* in_proj_w  = (const float*)d_in[2];
    const float* gate_proj_w= (const float*)d_in[3];
    const float* dt_w       = (const float*)d_in[4];
    const float* dt_b       = (const float*)d_in[5];
    const float* x_proj_w   = (const float*)d_in[6];
    const float* A_log      = (const float*)d_in[7];
    const float* Dp         = (const float*)d_in[8];
    const float* out_proj_w = (const float*)d_in[9];
    const float* ffn_norm_w = (const float*)d_in[10];
    const float* ffn_gate_w = (const float*)d_in[11];
    const float* ffn_up_w   = (const float*)d_in[12];
    const float* ffn_down_w = (const float*)d_in[13];
    float* out = (float*)d_out;

    float *h, *a, *bb, *y, *x2, *gg;
    cudaGetSymbolAddress((void**)&h,  g_h);
    cudaGetSymbolAddress((void**)&a,  g_a);
    cudaGetSymbolAddress((void**)&bb, g_b);
    cudaGetSymbolAddress((void**)&y,  g_y);
    cudaGetSymbolAddress((void**)&x2, g_x2);
    cudaGetSymbolAddress((void**)&gg, g_g);

    const int SM_BIG  = (256 + 128) * S * 4 * 2;   // 61440
    const int SM_DUAL = 3 * 128 * S * 4 * 2;       // 61440
    const int SM_SML  = (128 + 128) * S * 4 * 2;   // 40960

    cudaFuncSetAttribute(sgl_gemm<EP_SOFTPLUS,256,64,64>, cudaFuncAttributeMaxDynamicSharedMemorySize, SM_BIG);
    cudaFuncSetAttribute(dual_gemm<DEP_GATE>, cudaFuncAttributeMaxDynamicSharedMemorySize, SM_DUAL);
    cudaFuncSetAttribute(dual_gemm<DEP_SILU>, cudaFuncAttributeMaxDynamicSharedMemorySize, SM_DUAL);

    const dim3 blk(256);

    // 1. h = rmsnorm(x)
    rmsnorm_kernel<<<ROWS, blk>>>(x, norm1_w, h);

    // 2. z = (h @ in_proj^T) * sigmoid(h @ gate_proj^T)   [fused dual GEMM]
    dual_gemm<DEP_GATE><<<dim3(DIN/128, ROWS/128), blk, SM_DUAL>>>(h, in_proj_w, gate_proj_w, a, ROWS, DIN, DM);

    // 3. dt = softplus(z @ dt_w^T + dt_b)
    sgl_gemm<EP_SOFTPLUS,256,64,64><<<dim3(DIN/128, ROWS/256), blk, SM_BIG>>>(a, dt_w, nullptr, dt_b, bb, ROWS, DIN, DIN);

    // 4. BC = z @ x_proj^T
    bc_kernel<<<ROWS, blk>>>(x_proj_w);

    // 5. scan
    scan_kernel<<<(BATCH * DIN) / 16, blk>>>(A_log, Dp);

    // 6. x2 = x + y @ out_proj^T
    sgl_gemm<EP_ADD,128,64,32><<<dim3(DM/128, ROWS/128), blk, SM_SML>>>(y, out_proj_w, x, nullptr, x2, ROWS, DM, DIN);

    // 7. hn = rmsnorm(x2)
    rmsnorm_kernel<<<ROWS, blk>>>(x2, ffn_norm_w, h);

    // 8. FFN: gg = silu(hn @ Wg^T) * (hn @ Wu^T)   [fused dual GEMM]
    dual_gemm<DEP_SILU><<<dim3((FH+127)/128, ROWS/128), blk, SM_DUAL>>>(h, ffn_gate_w, ffn_up_w, gg, ROWS, FH, DM);

    // 9. out = x2 + gg @ Wd^T
    sgl_gemm<EP_ADD,128,64,32><<<dim3(DM/128, ROWS/128), blk, SM_SML>>>(gg, ffn_down_w, x2, nullptr, out, ROWS, DM, FH);
}

// round 5
// speedup vs baseline: 1.2135x; 1.2135x over previous
#include <cuda_runtime.h>
#include <math.h>
#include <stdint.h>

// Problem dims
constexpr int BATCH = 2;
constexpr int SEQ   = 1024;
constexpr int DM    = 1024;
constexpr int DIN   = 2048;
constexpr int NST   = 16;
constexpr int FH    = 2752;
constexpr int ROWS  = BATCH * SEQ;  // 2048

// Scratch
__device__ float g_h [ROWS * DM];
__device__ float g_a [ROWS * DIN];
__device__ float g_b [ROWS * DIN];
__device__ float g_y [ROWS * DIN];
__device__ float g_x2[ROWS * DM];
__device__ float g_bc[ROWS * 2 * NST];
__device__ float g_g [ROWS * FH];

constexpr int S = 20;            // smem row stride (floats), conflict-free frag pattern
constexpr int ASZ = 128 * S;     // floats per stage per matrix
constexpr int STAGES = 3;

__device__ __forceinline__ uint32_t s2u(const void* p) {
    uint32_t a;
    asm("{ .reg .u64 t; cvta.to.shared.u64 t, %1; cvt.u32.u64 %0, t; }" : "=r"(a) : "l"(p));
    return a;
}
__device__ __forceinline__ void cpa16(uint32_t dst, const float* src, int szbytes) {
    asm volatile("cp.async.cg.shared.global [%0], [%1], 16, %2;"
                 :: "r"(dst), "l"(src), "r"(szbytes));
}
#define CP_COMMIT() asm volatile("cp.async.commit_group;" ::: "memory")
#define CP_WAIT1()  asm volatile("cp.async.wait_group 1;" ::: "memory")

__device__ __forceinline__ void mma_tf32(float c[4],
                                         uint32_t a0, uint32_t a1, uint32_t a2, uint32_t a3,
                                         uint32_t b0, uint32_t b1) {
    asm volatile(
        "mma.sync.aligned.m16n8k8.row.col.f32.tf32.tf32.f32 "
        "{%0,%1,%2,%3}, {%4,%5,%6,%7}, {%8,%9}, {%0,%1,%2,%3};"
        : "+f"(c[0]), "+f"(c[1]), "+f"(c[2]), "+f"(c[3])
        : "r"(a0), "r"(a1), "r"(a2), "r"(a3), "r"(b0), "r"(b1));
}

enum { EP_NONE = 0, EP_ADD, EP_GATEMUL, EP_SOFTPLUS, EP_SILUMUL };

__device__ __forceinline__ float sigm(float x) { return 1.0f / (1.0f + expf(-x)); }
__device__ __forceinline__ float sftp(float x) { return (x > 20.0f) ? x : log1pf(expf(x)); }

// ---------------------------------------------------------------------------
// tf32 GEMM via cp.async 3-stage pipeline.
// C[M,N] = epilogue(A[M,K] @ W[N,K]^T).  BM=BN=128, BK=16, 8 warps (2x4),
// warp tile 64x32 (MT=4, NT=4).  fp32 fed raw to mma.tf32 (HW truncation).
// Optional folded side-block (last blockIdx.x): C2 = A @ W2^T with N2=32.
// ---------------------------------------------------------------------------
template<int EP>
__global__ void __launch_bounds__(256, 2) gemm_ca(
    const float* __restrict__ A, const float* __restrict__ W,
    const float* __restrict__ R, const float* __restrict__ bias,
    float* __restrict__ C, int M, int N, int K,
    const float* __restrict__ W2, float* __restrict__ C2)
{
    constexpr int WM = 64, WN = 32, MT = 4, NT = 4;
    extern __shared__ float sm[];
    float* As = sm;
    float* Bs = sm + STAGES * ASZ;
    const uint32_t sbA = s2u(As), sbB = s2u(Bs);

    const int tid  = threadIdx.x;
    const int wid  = tid >> 5, lane = tid & 31;
    const int wm   = wid >> 2, wn = wid & 3;
    const int bm   = blockIdx.y << 7;
    const int bx   = blockIdx.x;
    const bool isbc = (W2 != nullptr) && (bx == (int)gridDim.x - 1);
    const int bn   = isbc ? 0 : (bx << 7);
    const int Nw   = isbc ? 32 : N;          // valid weight rows
    const float* Wk = isbc ? W2 : W;
    const int lr   = lane >> 2, lc = lane & 3;

    float acc[MT][NT][4];
    #pragma unroll
    for (int i = 0; i < MT; i++)
        #pragma unroll
        for (int j = 0; j < NT; j++)
            #pragma unroll
            for (int q = 0; q < 4; q++) acc[i][j][q] = 0.0f;

    const int row0 = tid >> 2;               // +64 for second chunk
    const int kcol = (tid & 3) << 2;
    const int NS   = K >> 4;

    // Per-thread source rows (B clamped; zero-fill via src_size=0)
    const int ar0 = bm + row0, ar1 = bm + row0 + 64;
    const int b0v = (bn + row0 < Nw) ? 16 : 0;
    const int b1v = (bn + row0 + 64 < Nw) ? 16 : 0;
    const float* asrc0 = A + (size_t)ar0 * K + kcol;
    const float* asrc1 = A + (size_t)ar1 * K + kcol;
    const float* bsrc0 = Wk + (size_t)min(bn + row0,      Nw - 1) * K + kcol;
    const float* bsrc1 = Wk + (size_t)min(bn + row0 + 64, Nw - 1) * K + kcol;
    const uint32_t dA0 = sbA + (uint32_t)((row0 * S + kcol) << 2);
    const uint32_t dA1 = sbA + (uint32_t)(((row0 + 64) * S + kcol) << 2);
    const uint32_t dB0 = sbB + (uint32_t)((row0 * S + kcol) << 2);
    const uint32_t dB1 = sbB + (uint32_t)(((row0 + 64) * S + kcol) << 2);
    constexpr uint32_t STGB = ASZ * 4;       // stage stride in bytes

    auto issue = [&](int st, int k0) {
        cpa16(dA0 + st * STGB, asrc0 + k0, 16);
        cpa16(dA1 + st * STGB, asrc1 + k0, 16);
        cpa16(dB0 + st * STGB, bsrc0 + k0, b0v);
        cpa16(dB1 + st * STGB, bsrc1 + k0, b1v);
        CP_COMMIT();
    };

    issue(0, 0);
    issue(1, 16);

    const int fa_base = (wm * WM + lr) * S + lc;
    const int fb_base = (wn * WN + lr) * S + lc;

    for (int ks = 0; ks < NS; ks++) {
        const int buf = ks % STAGES;
        CP_WAIT1();
        __syncthreads();

        if (ks + 2 < NS) issue((ks + 2) % STAGES, (ks + 2) << 4);
        else CP_COMMIT();   // keep group accounting uniform

        const uint32_t* Asb = (const uint32_t*)(As + buf * ASZ);
        const uint32_t* Bsb = (const uint32_t*)(Bs + buf * ASZ);
        #pragma unroll
        for (int kc = 0; kc < 2; kc++) {
            uint32_t af[MT][4], bf[NT][2];
            #pragma unroll
            for (int tm = 0; tm < MT; tm++) {
                const int base = fa_base + tm * 16 * S + kc * 8;
                af[tm][0] = Asb[base];
                af[tm][1] = Asb[base + 8 * S];
                af[tm][2] = Asb[base + 4];
                af[tm][3] = Asb[base + 8 * S + 4];
            }
            #pragma unroll
            for (int tn = 0; tn < NT; tn++) {
                const int base = fb_base + tn * 8 * S + kc * 8;
                bf[tn][0] = Bsb[base];
                bf[tn][1] = Bsb[base + 4];
            }
            #pragma unroll
            for (int tm = 0; tm < MT; tm++)
                #pragma unroll
                for (int tn = 0; tn < NT; tn++)
                    mma_tf32(acc[tm][tn], af[tm][0], af[tm][1], af[tm][2], af[tm][3],
                             bf[tn][0], bf[tn][1]);
        }
        __syncthreads();
    }

    // Epilogue
    if (isbc) {
        #pragma unroll
        for (int tm = 0; tm < MT; tm++) {
            const int row = bm + wm * WM + tm * 16 + lr;
            #pragma unroll
            for (int tn = 0; tn < NT; tn++) {
                const int col = wn * WN + tn * 8 + lc * 2;
                if (col < 32) {
                    *(float2*)(C2 + (size_t)row * 32 + col) =
                        make_float2(acc[tm][tn][0], acc[tm][tn][1]);
                    *(float2*)(C2 + (size_t)(row + 8) * 32 + col) =
                        make_float2(acc[tm][tn][2], acc[tm][tn][3]);
                }
            }
        }
        return;
    }

    #pragma unroll
    for (int tm = 0; tm < MT; tm++) {
        const int row = bm + wm * WM + tm * 16 + lr;
        #pragma unroll
        for (int tn = 0; tn < NT; tn++) {
            const int col = bn + wn * WN + tn * 8 + lc * 2;
            if (col < N) {
                const size_t o0 = (size_t)row * N + col;
                const size_t o1 = (size_t)(row + 8) * N + col;
                float2 v0 = make_float2(acc[tm][tn][0], acc[tm][tn][1]);
                float2 v1 = make_float2(acc[tm][tn][2], acc[tm][tn][3]);
                if (EP == EP_ADD) {
                    const float2 r0 = *(const float2*)(R + o0);
                    const float2 r1 = *(const float2*)(R + o1);
                    v0.x += r0.x; v0.y += r0.y; v1.x += r1.x; v1.y += r1.y;
                } else if (EP == EP_GATEMUL) {
                    const float2 r0 = *(const float2*)(R + o0);
                    const float2 r1 = *(const float2*)(R + o1);
                    v0.x = r0.x * sigm(v0.x); v0.y = r0.y * sigm(v0.y);
                    v1.x = r1.x * sigm(v1.x); v1.y = r1.y * sigm(v1.y);
                } else if (EP == EP_SOFTPLUS) {
                    const float2 bv = *(const float2*)(bias + col);
                    v0.x = sftp(v0.x + bv.x); v0.y = sftp(v0.y + bv.y);
                    v1.x = sftp(v1.x + bv.x); v1.y = sftp(v1.y + bv.y);
                } else if (EP == EP_SILUMUL) {
                    const float2 r0 = *(const float2*)(R + o0);
                    const float2 r1 = *(const float2*)(R + o1);
                    v0.x = r0.x * sigm(r0.x) * v0.x; v0.y = r0.y * sigm(r0.y) * v0.y;
                    v1.x = r1.x * sigm(r1.x) * v1.x; v1.y = r1.y * sigm(r1.y) * v1.y;
                }
                *(float2*)(C + o0) = v0;
                *(float2*)(C + o1) = v1;
            }
        }
    }
}

// ---------------------------------------------------------------------------
// RMSNorm
// ---------------------------------------------------------------------------
__global__ void __launch_bounds__(256) rmsnorm_kernel(
    const float* __restrict__ x, const float* __restrict__ w, float* __restrict__ out)
{
    __shared__ float red[8];
    const int row = blockIdx.x;
    const int tid = threadIdx.x;
    const float4 v = ((const float4*)(x + (size_t)row * DM))[tid];
    float s = v.x*v.x + v.y*v.y + v.z*v.z + v.w*v.w;
    #pragma unroll
    for (int o = 16; o; o >>= 1) s += __shfl_xor_sync(0xffffffffu, s, o);
    if ((tid & 31) == 0) red[tid >> 5] = s;
    __syncthreads();
    if (tid < 8) {
        float t = red[tid];
        #pragma unroll
        for (int o = 4; o; o >>= 1) t += __shfl_xor_sync(0xffu, t, o);
        if (tid == 0) red[0] = t;
    }
    __syncthreads();
    const float scale = rsqrtf(red[0] * (1.0f / DM) + 1e-6f);
    const float4 wv = ((const float4*)w)[tid];
    float4 o4;
    o4.x = v.x * scale * wv.x; o4.y = v.y * scale * wv.y;
    o4.z = v.z * scale * wv.z; o4.w = v.w * scale * wv.w;
    ((float4*)(out + (size_t)row * DM))[tid] = o4;
}

// ---------------------------------------------------------------------------
// Selective scan (16 lanes per channel), unrolled x4 for load MLP
// ---------------------------------------------------------------------------
__global__ void __launch_bounds__(256) scan_kernel(
    const float* __restrict__ A_log, const float* __restrict__ Dp)
{
    const int tid = threadIdx.x;
    const int ch  = blockIdx.x * 16 + (tid >> 4);
    const int n   = tid & 15;
    const int b   = ch / DIN;
    const int e   = ch % DIN;

    const float An  = -__expf(A_log[(size_t)e * NST + n]);
    const float dpe = Dp[e];

    const float* dtp = g_b  + (size_t)b * SEQ * DIN + e;
    const float* zp  = g_a  + (size_t)b * SEQ * DIN + e;
    const float* bcp = g_bc + (size_t)b * SEQ * 32;
    float*       yp  = g_y  + (size_t)b * SEQ * DIN + e;

    float state = 0.0f;
    #pragma unroll 4
    for (int t = 0; t < SEQ; t++) {
        const float dtv = __ldg(dtp + (size_t)t * DIN);
        const float zv  = __ldg(zp  + (size_t)t * DIN);
        const float Bn  = bcp[t * 32 + n];
        const float Cn  = bcp[t * 32 + 16 + n];
        state = __expf(dtv * An) * state + dtv * zv * Bn;
        float s = state * Cn;
        s += __shfl_xor_sync(0xffffffffu, s, 8);
        s += __shfl_xor_sync(0xffffffffu, s, 4);
        s += __shfl_xor_sync(0xffffffffu, s, 2);
        s += __shfl_xor_sync(0xffffffffu, s, 1);
        if (n == 0) yp[(size_t)t * DIN] = s + zv * dpe;
    }
}

// ---------------------------------------------------------------------------
// Launch
// ---------------------------------------------------------------------------
extern "C" void kernel_launch(void* const* d_in, const int* in_sizes, int n_in,
                              void* d_out, int out_size)
{
    const float* x          = (const float*)d_in[0];
    const float* norm1_w    = (const float*)d_in[1];
    const float* in_proj_w  = (const float*)d_in[2];
    const float* gate_proj_w= (const float*)d_in[3];
    const float* dt_w       = (const float*)d_in[4];
    const float* dt_b       = (const float*)d_in[5];
    const float* x_proj_w   = (const float*)d_in[6];
    const float* A_log      = (const float*)d_in[7];
    const float* Dp         = (const float*)d_in[8];
    const float* out_proj_w = (const float*)d_in[9];
    const float* ffn_norm_w = (const float*)d_in[10];
    const float* ffn_gate_w = (const float*)d_in[11];
    const float* ffn_up_w   = (const float*)d_in[12];
    const float* ffn_down_w = (const float*)d_in[13];
    float* out = (float*)d_out;

    float *h, *a, *bb, *y, *x2, *gg, *bc;
    cudaGetSymbolAddress((void**)&h,  g_h);
    cudaGetSymbolAddress((void**)&a,  g_a);
    cudaGetSymbolAddress((void**)&bb, g_b);
    cudaGetSymbolAddress((void**)&y,  g_y);
    cudaGetSymbolAddress((void**)&x2, g_x2);
    cudaGetSymbolAddress((void**)&gg, g_g);
    cudaGetSymbolAddress((void**)&bc, g_bc);

    const int SMEM = STAGES * ASZ * 2 * 4;   // 61440 bytes

    cudaFuncSetAttribute(gemm_ca<EP_NONE>,     cudaFuncAttributeMaxDynamicSharedMemorySize, SMEM);
    cudaFuncSetAttribute(gemm_ca<EP_ADD>,      cudaFuncAttributeMaxDynamicSharedMemorySize, SMEM);
    cudaFuncSetAttribute(gemm_ca<EP_GATEMUL>,  cudaFuncAttributeMaxDynamicSharedMemorySize, SMEM);
    cudaFuncSetAttribute(gemm_ca<EP_SOFTPLUS>, cudaFuncAttributeMaxDynamicSharedMemorySize, SMEM);
    cudaFuncSetAttribute(gemm_ca<EP_SILUMUL>,  cudaFuncAttributeMaxDynamicSharedMemorySize, SMEM);

    const dim3 blk(256);

    // 1. h = rmsnorm(x)
    rmsnorm_kernel<<<ROWS, blk>>>(x, norm1_w, h);

    // 2. z = h @ in_proj^T ; z *= sigmoid(h @ gate_proj^T)
    gemm_ca<EP_NONE>   <<<dim3(DIN/128, ROWS/128), blk, SMEM>>>(h, in_proj_w,   nullptr, nullptr, a, ROWS, DIN, DM, nullptr, nullptr);
    gemm_ca<EP_GATEMUL><<<dim3(DIN/128, ROWS/128), blk, SMEM>>>(h, gate_proj_w, a,       nullptr, a, ROWS, DIN, DM, nullptr, nullptr);

    // 3. dt = softplus(z @ dt_w^T + dt_b)  [+ folded BC = z @ x_proj^T]
    gemm_ca<EP_SOFTPLUS><<<dim3(DIN/128 + 1, ROWS/128), blk, SMEM>>>(a, dt_w, nullptr, dt_b, bb, ROWS, DIN, DIN, x_proj_w, bc);

    // 4. scan
    scan_kernel<<<(BATCH * DIN) / 16, blk>>>(A_log, Dp);

    // 5. x2 = x + y @ out_proj^T
    gemm_ca<EP_ADD><<<dim3(DM/128, ROWS/128), blk, SMEM>>>(y, out_proj_w, x, nullptr, x2, ROWS, DM, DIN, nullptr, nullptr);

    // 6. hn = rmsnorm(x2)
    rmsnorm_kernel<<<ROWS, blk>>>(x2, ffn_norm_w, h);

    // 7. FFN: gg = silu(hn @ Wg^T) * (hn @ Wu^T)
    gemm_ca<EP_NONE>   <<<dim3((FH+127)/128, ROWS/128), blk, SMEM>>>(h, ffn_gate_w, nullptr, nullptr, gg, ROWS, FH, DM, nullptr, nullptr);
    gemm_ca<EP_SILUMUL><<<dim3((FH+127)/128, ROWS/128), blk, SMEM>>>(h, ffn_up_w,   gg,      nullptr, gg, ROWS, FH, DM, nullptr, nullptr);

    // 8. out = x2 + gg @ Wd^T
    gemm_ca<EP_ADD><<<dim3(DM/128, ROWS/128), blk, SMEM>>>(gg, ffn_down_w, x2, nullptr, out, ROWS, DM, FH, nullptr, nullptr);
}

// round 6
// speedup vs baseline: 1.2209x; 1.0060x over previous
#include <cuda_runtime.h>
#include <math.h>
#include <stdint.h>

// Problem dims
constexpr int BATCH = 2;
constexpr int SEQ   = 1024;
constexpr int DM    = 1024;
constexpr int DIN   = 2048;
constexpr int NST   = 16;
constexpr int FH    = 2752;
constexpr int ROWS  = BATCH * SEQ;  // 2048

// Scratch
__device__ float g_h [ROWS * DM];
__device__ float g_a [ROWS * DIN];
__device__ float g_b [ROWS * DIN];
__device__ float g_y [ROWS * DIN];
__device__ float g_x2[ROWS * DM];
__device__ float g_bc[ROWS * 2 * NST];
__device__ float g_g [ROWS * FH];

constexpr int S = 20;            // smem row stride (floats), conflict-free frag pattern
constexpr int ASZ = 128 * S;     // floats per stage per matrix
constexpr int STAGES = 4;

// tf32 HW conversion truncates (RZ): each operand's magnitude biased low by
// ~2^-12 on average -> product low by ~2^-11.  Compensate in epilogue.
constexpr float CBIAS = 1.00048828125f;   // 1 + 2^-11

__device__ __forceinline__ uint32_t s2u(const void* p) {
    uint32_t a;
    asm("{ .reg .u64 t; cvta.to.shared.u64 t, %1; cvt.u32.u64 %0, t; }" : "=r"(a) : "l"(p));
    return a;
}
__device__ __forceinline__ void cpa16(uint32_t dst, const float* src, int szbytes) {
    asm volatile("cp.async.cg.shared.global [%0], [%1], 16, %2;"
                 :: "r"(dst), "l"(src), "r"(szbytes));
}
#define CP_COMMIT() asm volatile("cp.async.commit_group;" ::: "memory")
#define CP_WAIT2()  asm volatile("cp.async.wait_group 2;" ::: "memory")

__device__ __forceinline__ void mma_tf32(float c[4],
                                         uint32_t a0, uint32_t a1, uint32_t a2, uint32_t a3,
                                         uint32_t b0, uint32_t b1) {
    asm volatile(
        "mma.sync.aligned.m16n8k8.row.col.f32.tf32.tf32.f32 "
        "{%0,%1,%2,%3}, {%4,%5,%6,%7}, {%8,%9}, {%0,%1,%2,%3};"
        : "+f"(c[0]), "+f"(c[1]), "+f"(c[2]), "+f"(c[3])
        : "r"(a0), "r"(a1), "r"(a2), "r"(a3), "r"(b0), "r"(b1));
}

enum { EP_NONE = 0, EP_ADD, EP_GATEMUL, EP_SOFTPLUS, EP_SILUMUL };

__device__ __forceinline__ float sigm(float x) { return 1.0f / (1.0f + expf(-x)); }
__device__ __forceinline__ float sftp(float x) { return (x > 20.0f) ? x : log1pf(expf(x)); }

// ---------------------------------------------------------------------------
// tf32 GEMM via cp.async 4-stage pipeline, ONE barrier per K-iter.
// C[M,N] = epilogue(A[M,K] @ W[N,K]^T).  BM=BN=128, BK=16, 8 warps (2x4),
// warp tile 64x32 (MT=4, NT=4).
// Optional folded side-block (last blockIdx.x): C2 = A @ W2^T with N2=32.
// ---------------------------------------------------------------------------
template<int EP>
__global__ void __launch_bounds__(256, 2) gemm_ca(
    const float* __restrict__ A, const float* __restrict__ W,
    const float* __restrict__ R, const float* __restrict__ bias,
    float* __restrict__ C, int M, int N, int K,
    const float* __restrict__ W2, float* __restrict__ C2)
{
    constexpr int WM = 64, WN = 32, MT = 4, NT = 4;
    extern __shared__ float sm[];
    float* As = sm;
    float* Bs = sm + STAGES * ASZ;
    const uint32_t sbA = s2u(As), sbB = s2u(Bs);

    const int tid  = threadIdx.x;
    const int wid  = tid >> 5, lane = tid & 31;
    const int wm   = wid >> 2, wn = wid & 3;
    const int bm   = blockIdx.y << 7;
    const int bx   = blockIdx.x;
    const bool isbc = (W2 != nullptr) && (bx == (int)gridDim.x - 1);
    const int bn   = isbc ? 0 : (bx << 7);
    const int Nw   = isbc ? 32 : N;
    const float* Wk = isbc ? W2 : W;
    const int lr   = lane >> 2, lc = lane & 3;

    float acc[MT][NT][4];
    #pragma unroll
    for (int i = 0; i < MT; i++)
        #pragma unroll
        for (int j = 0; j < NT; j++)
            #pragma unroll
            for (int q = 0; q < 4; q++) acc[i][j][q] = 0.0f;

    const int row0 = tid >> 2;
    const int kcol = (tid & 3) << 2;
    const int NS   = K >> 4;

    const int b0v = (bn + row0 < Nw) ? 16 : 0;
    const int b1v = (bn + row0 + 64 < Nw) ? 16 : 0;
    const float* asrc0 = A  + (size_t)(bm + row0) * K + kcol;
    const float* asrc1 = A  + (size_t)(bm + row0 + 64) * K + kcol;
    const float* bsrc0 = Wk + (size_t)min(bn + row0,      Nw - 1) * K + kcol;
    const float* bsrc1 = Wk + (size_t)min(bn + row0 + 64, Nw - 1) * K + kcol;
    const uint32_t dA0 = sbA + (uint32_t)((row0 * S + kcol) << 2);
    const uint32_t dA1 = sbA + (uint32_t)(((row0 + 64) * S + kcol) << 2);
    const uint32_t dB0 = sbB + (uint32_t)((row0 * S + kcol) << 2);
    const uint32_t dB1 = sbB + (uint32_t)(((row0 + 64) * S + kcol) << 2);
    constexpr uint32_t STGB = ASZ * 4;

    auto issue = [&](int st, int k0) {
        cpa16(dA0 + st * STGB, asrc0 + k0, 16);
        cpa16(dA1 + st * STGB, asrc1 + k0, 16);
        cpa16(dB0 + st * STGB, bsrc0 + k0, b0v);
        cpa16(dB1 + st * STGB, bsrc1 + k0, b1v);
        CP_COMMIT();
    };

    issue(0, 0);
    issue(1, 16);
    issue(2, 32);

    const int fa_base = (wm * WM + lr) * S + lc;
    const int fb_base = (wn * WN + lr) * S + lc;

    for (int ks = 0; ks < NS; ks++) {
        const int buf = ks & 3;
        CP_WAIT2();
        __syncthreads();   // single barrier: all warps done reading stage (ks-1)&3

        if (ks + 3 < NS) issue((ks + 3) & 3, (ks + 3) << 4);
        else CP_COMMIT();  // keep group accounting uniform

        const uint32_t* Asb = (const uint32_t*)(As + buf * ASZ);
        const uint32_t* Bsb = (const uint32_t*)(Bs + buf * ASZ);

        uint32_t af[2][MT][4], bf[2][NT][2];
        #pragma unroll
        for (int kc = 0; kc < 2; kc++) {
            #pragma unroll
            for (int tm = 0; tm < MT; tm++) {
                const int base = fa_base + tm * 16 * S + kc * 8;
                af[kc][tm][0] = Asb[base];
                af[kc][tm][1] = Asb[base + 8 * S];
                af[kc][tm][2] = Asb[base + 4];
                af[kc][tm][3] = Asb[base + 8 * S + 4];
            }
            #pragma unroll
            for (int tn = 0; tn < NT; tn++) {
                const int base = fb_base + tn * 8 * S + kc * 8;
                bf[kc][tn][0] = Bsb[base];
                bf[kc][tn][1] = Bsb[base + 4];
            }
        }
        #pragma unroll
        for (int kc = 0; kc < 2; kc++)
            #pragma unroll
            for (int tm = 0; tm < MT; tm++)
                #pragma unroll
                for (int tn = 0; tn < NT; tn++)
                    mma_tf32(acc[tm][tn],
                             af[kc][tm][0], af[kc][tm][1], af[kc][tm][2], af[kc][tm][3],
                             bf[kc][tn][0], bf[kc][tn][1]);
    }

    // Epilogue (CBIAS compensates tf32 truncation bias)
    if (isbc) {
        #pragma unroll
        for (int tm = 0; tm < MT; tm++) {
            const int row = bm + wm * WM + tm * 16 + lr;
            #pragma unroll
            for (int tn = 0; tn < NT; tn++) {
                const int col = wn * WN + tn * 8 + lc * 2;
                if (col < 32) {
                    *(float2*)(C2 + (size_t)row * 32 + col) =
                        make_float2(acc[tm][tn][0] * CBIAS, acc[tm][tn][1] * CBIAS);
                    *(float2*)(C2 + (size_t)(row + 8) * 32 + col) =
                        make_float2(acc[tm][tn][2] * CBIAS, acc[tm][tn][3] * CBIAS);
                }
            }
        }
        return;
    }

    #pragma unroll
    for (int tm = 0; tm < MT; tm++) {
        const int row = bm + wm * WM + tm * 16 + lr;
        #pragma unroll
        for (int tn = 0; tn < NT; tn++) {
            const int col = bn + wn * WN + tn * 8 + lc * 2;
            if (col < N) {
                const size_t o0 = (size_t)row * N + col;
                const size_t o1 = (size_t)(row + 8) * N + col;
                float2 v0 = make_float2(acc[tm][tn][0] * CBIAS, acc[tm][tn][1] * CBIAS);
                float2 v1 = make_float2(acc[tm][tn][2] * CBIAS, acc[tm][tn][3] * CBIAS);
                if (EP == EP_ADD) {
                    const float2 r0 = *(const float2*)(R + o0);
                    const float2 r1 = *(const float2*)(R + o1);
                    v0.x += r0.x; v0.y += r0.y; v1.x += r1.x; v1.y += r1.y;
                } else if (EP == EP_GATEMUL) {
                    const float2 r0 = *(const float2*)(R + o0);
                    const float2 r1 = *(const float2*)(R + o1);
                    v0.x = r0.x * sigm(v0.x); v0.y = r0.y * sigm(v0.y);
                    v1.x = r1.x * sigm(v1.x); v1.y = r1.y * sigm(v1.y);
                } else if (EP == EP_SOFTPLUS) {
                    const float2 bv = *(const float2*)(bias + col);
                    v0.x = sftp(v0.x + bv.x); v0.y = sftp(v0.y + bv.y);
                    v1.x = sftp(v1.x + bv.x); v1.y = sftp(v1.y + bv.y);
                } else if (EP == EP_SILUMUL) {
                    const float2 r0 = *(const float2*)(R + o0);
                    const float2 r1 = *(const float2*)(R + o1);
                    v0.x = r0.x * sigm(r0.x) * v0.x; v0.y = r0.y * sigm(r0.y) * v0.y;
                    v1.x = r1.x * sigm(r1.x) * v1.x; v1.y = r1.y * sigm(r1.y) * v1.y;
                }
                *(float2*)(C + o0) = v0;
                *(float2*)(C + o1) = v1;
            }
        }
    }
}

// ---------------------------------------------------------------------------
// RMSNorm
// ---------------------------------------------------------------------------
__global__ void __launch_bounds__(256) rmsnorm_kernel(
    const float* __restrict__ x, const float* __restrict__ w, float* __restrict__ out)
{
    __shared__ float red[8];
    const int row = blockIdx.x;
    const int tid = threadIdx.x;
    const float4 v = ((const float4*)(x + (size_t)row * DM))[tid];
    float s = v.x*v.x + v.y*v.y + v.z*v.z + v.w*v.w;
    #pragma unroll
    for (int o = 16; o; o >>= 1) s += __shfl_xor_sync(0xffffffffu, s, o);
    if ((tid & 31) == 0) red[tid >> 5] = s;
    __syncthreads();
    if (tid < 8) {
        float t = red[tid];
        #pragma unroll
        for (int o = 4; o; o >>= 1) t += __shfl_xor_sync(0xffu, t, o);
        if (tid == 0) red[0] = t;
    }
    __syncthreads();
    const float scale = rsqrtf(red[0] * (1.0f / DM) + 1e-6f);
    const float4 wv = ((const float4*)w)[tid];
    float4 o4;
    o4.x = v.x * scale * wv.x; o4.y = v.y * scale * wv.y;
    o4.z = v.z * scale * wv.z; o4.w = v.w * scale * wv.w;
    ((float4*)(out + (size_t)row * DM))[tid] = o4;
}

// ---------------------------------------------------------------------------
// Selective scan (16 lanes per channel)
// ---------------------------------------------------------------------------
__global__ void __launch_bounds__(256) scan_kernel(
    const float* __restrict__ A_log, const float* __restrict__ Dp)
{
    const int tid = threadIdx.x;
    const int ch  = blockIdx.x * 16 + (tid >> 4);
    const int n   = tid & 15;
    const int b   = ch / DIN;
    const int e   = ch % DIN;

    const float An  = -__expf(A_log[(size_t)e * NST + n]);
    const float dpe = Dp[e];

    const float* dtp = g_b  + (size_t)b * SEQ * DIN + e;
    const float* zp  = g_a  + (size_t)b * SEQ * DIN + e;
    const float* bcp = g_bc + (size_t)b * SEQ * 32;
    float*       yp  = g_y  + (size_t)b * SEQ * DIN + e;

    float state = 0.0f;
    #pragma unroll 4
    for (int t = 0; t < SEQ; t++) {
        const float dtv = __ldg(dtp + (size_t)t * DIN);
        const float zv  = __ldg(zp  + (size_t)t * DIN);
        const float Bn  = bcp[t * 32 + n];
        const float Cn  = bcp[t * 32 + 16 + n];
        state = __expf(dtv * An) * state + dtv * zv * Bn;
        float s = state * Cn;
        s += __shfl_xor_sync(0xffffffffu, s, 8);
        s += __shfl_xor_sync(0xffffffffu, s, 4);
        s += __shfl_xor_sync(0xffffffffu, s, 2);
        s += __shfl_xor_sync(0xffffffffu, s, 1);
        if (n == 0) yp[(size_t)t * DIN] = s + zv * dpe;
    }
}

// ---------------------------------------------------------------------------
// Launch
// ---------------------------------------------------------------------------
extern "C" void kernel_launch(void* const* d_in, const int* in_sizes, int n_in,
                              void* d_out, int out_size)
{
    const float* x          = (const float*)d_in[0];
    const float* norm1_w    = (const float*)d_in[1];
    const float* in_proj_w  = (const float*)d_in[2];
    const float* gate_proj_w= (const float*)d_in[3];
    const float* dt_w       = (const float*)d_in[4];
    const float* dt_b       = (const float*)d_in[5];
    const float* x_proj_w   = (const float*)d_in[6];
    const float* A_log      = (const float*)d_in[7];
    const float* Dp         = (const float*)d_in[8];
    const float* out_proj_w = (const float*)d_in[9];
    const float* ffn_norm_w = (const float*)d_in[10];
    const float* ffn_gate_w = (const float*)d_in[11];
    const float* ffn_up_w   = (const float*)d_in[12];
    const float* ffn_down_w = (const float*)d_in[13];
    float* out = (float*)d_out;

    float *h, *a, *bb, *y, *x2, *gg, *bc;
    cudaGetSymbolAddress((void**)&h,  g_h);
    cudaGetSymbolAddress((void**)&a,  g_a);
    cudaGetSymbolAddress((void**)&bb, g_b);
    cudaGetSymbolAddress((void**)&y,  g_y);
    cudaGetSymbolAddress((void**)&x2, g_x2);
    cudaGetSymbolAddress((void**)&gg, g_g);
    cudaGetSymbolAddress((void**)&bc, g_bc);

    const int SMEM = STAGES * ASZ * 2 * 4;   // 81920 bytes

    cudaFuncSetAttribute(gemm_ca<EP_NONE>,     cudaFuncAttributeMaxDynamicSharedMemorySize, SMEM);
    cudaFuncSetAttribute(gemm_ca<EP_ADD>,      cudaFuncAttributeMaxDynamicSharedMemorySize, SMEM);
    cudaFuncSetAttribute(gemm_ca<EP_GATEMUL>,  cudaFuncAttributeMaxDynamicSharedMemorySize, SMEM);
    cudaFuncSetAttribute(gemm_ca<EP_SOFTPLUS>, cudaFuncAttributeMaxDynamicSharedMemorySize, SMEM);
    cudaFuncSetAttribute(gemm_ca<EP_SILUMUL>,  cudaFuncAttributeMaxDynamicSharedMemorySize, SMEM);

    const dim3 blk(256);

    // 1. h = rmsnorm(x)
    rmsnorm_kernel<<<ROWS, blk>>>(x, norm1_w, h);

    // 2. z = h @ in_proj^T ; z *= sigmoid(h @ gate_proj^T)
    gemm_ca<EP_NONE>   <<<dim3(DIN/128, ROWS/128), blk, SMEM>>>(h, in_proj_w,   nullptr, nullptr, a, ROWS, DIN, DM, nullptr, nullptr);
    gemm_ca<EP_GATEMUL><<<dim3(DIN/128, ROWS/128), blk, SMEM>>>(h, gate_proj_w, a,       nullptr, a, ROWS, DIN, DM, nullptr, nullptr);

    // 3. dt = softplus(z @ dt_w^T + dt_b)  [+ folded BC = z @ x_proj^T]
    gemm_ca<EP_SOFTPLUS><<<dim3(DIN/128 + 1, ROWS/128), blk, SMEM>>>(a, dt_w, nullptr, dt_b, bb, ROWS, DIN, DIN, x_proj_w, bc);

    // 4. scan
    scan_kernel<<<(BATCH * DIN) / 16, blk>>>(A_log, Dp);

    // 5. x2 = x + y @ out_proj^T
    gemm_ca<EP_ADD><<<dim3(DM/128, ROWS/128), blk, SMEM>>>(y, out_proj_w, x, nullptr, x2, ROWS, DM, DIN, nullptr, nullptr);

    // 6. hn = rmsnorm(x2)
    rmsnorm_kernel<<<ROWS, blk>>>(x2, ffn_norm_w, h);

    // 7. FFN: gg = silu(hn @ Wg^T) * (hn @ Wu^T)
    gemm_ca<EP_NONE>   <<<dim3((FH+127)/128, ROWS/128), blk, SMEM>>>(h, ffn_gate_w, nullptr, nullptr, gg, ROWS, FH, DM, nullptr, nullptr);
    gemm_ca<EP_SILUMUL><<<dim3((FH+127)/128, ROWS/128), blk, SMEM>>>(h, ffn_up_w,   gg,      nullptr, gg, ROWS, FH, DM, nullptr, nullptr);

    // 8. out = x2 + gg @ Wd^T
    gemm_ca<EP_ADD><<<dim3(DM/128, ROWS/128), blk, SMEM>>>(gg, ffn_down_w, x2, nullptr, out, ROWS, DM, FH, nullptr, nullptr);
}